// round 7
// baseline (speedup 1.0000x reference)
#include <cuda_runtime.h>
#include <cuda_bf16.h>
#include <cstdint>

// ============================================================================
// Problem constants
// ============================================================================
#define B_ROWS 4096
#define D_DIM  1024
#define TEMP   0.2f

// GEMM tiling: sim[4096,4096] = z_j (M side) @ z_i^T (N side)
#define TM 256
#define TN 128
#define KC 64                            // bf16 per K-chunk = 128 bytes/row
#define NCHUNK (D_DIM / KC)              // 16
#define CHUNK_MAT_BYTES (B_ROWS * 128)   // 524288 bytes per chunk-slab per matrix

#define A_TILE_BYTES (TM * 128)          // 32768
#define B_TILE_BYTES (TN * 128)          // 16384
#define STAGE_BYTES  (A_TILE_BYTES + B_TILE_BYTES)   // 49152
#define NSTAGE 3

// SMEM: [0..1024) control/reduction, then 3 stages of (A tile | B tile)
#define SMEM_TOTAL (1024 + NSTAGE * STAGE_BYTES)     // 148480

#define N_CTAS ((B_ROWS / TM) * (B_ROWS / TN))       // 16 * 32 = 512

// ============================================================================
// Device scratch (static __device__ globals — no allocation allowed)
// Layout: chunk-major, pre-swizzled (SW128): within chunk slab,
//   byte offset = SWZ128(row*128 + kbyte). cp.async then copies verbatim and
//   smem lands ldmatrix-ready with zero bank conflicts.
// ============================================================================
__device__ __align__(1024) __nv_bfloat16 g_zj[(size_t)B_ROWS * D_DIM];  // M side (emb_j)
__device__ __align__(1024) __nv_bfloat16 g_zi[(size_t)B_ROWS * D_DIM];  // N side (emb_i)
__device__ float g_partials[2 * N_CTAS];

// ============================================================================
// PTX helpers — base-target only (sm_80-class): cp.async, ldmatrix, mma.sync
// ============================================================================
__device__ __forceinline__ uint32_t smem_to_u32(const void* smem_ptr) {
    uint32_t addr;
    asm("{ .reg .u64 tmp; cvta.to.shared.u64 tmp, %1; cvt.u32.u64 %0, tmp; }"
        : "=r"(addr) : "l"(smem_ptr));
    return addr;
}

#define SWZ128(o) ((o) ^ (((o) >> 3) & 0x70))

__device__ __forceinline__ void cp_async16(uint32_t dst, const void* src) {
    asm volatile("cp.async.cg.shared.global [%0], [%1], 16;"
        :: "r"(dst), "l"(src) : "memory");
}
#define CP_COMMIT() asm volatile("cp.async.commit_group;" ::: "memory")
#define CP_WAIT(n)  asm volatile("cp.async.wait_group %0;" :: "n"(n) : "memory")

__device__ __forceinline__ void ldsm_x4(uint32_t* r, uint32_t addr) {
    asm volatile("ldmatrix.sync.aligned.m8n8.x4.shared.b16 {%0,%1,%2,%3}, [%4];"
        : "=r"(r[0]), "=r"(r[1]), "=r"(r[2]), "=r"(r[3]) : "r"(addr));
}

__device__ __forceinline__ void mma16816(float* d, const uint32_t* a, const uint32_t* b) {
    asm volatile(
        "mma.sync.aligned.m16n8k16.row.col.f32.bf16.bf16.f32 "
        "{%0,%1,%2,%3}, {%4,%5,%6,%7}, {%8,%9}, {%0,%1,%2,%3};"
        : "+f"(d[0]), "+f"(d[1]), "+f"(d[2]), "+f"(d[3])
        : "r"(a[0]), "r"(a[1]), "r"(a[2]), "r"(a[3]), "r"(b[0]), "r"(b[1]));
}

// ============================================================================
// Kernel 1: row L2-normalize fp32 -> bf16 scratch (chunk-major, pre-swizzled)
// 8192 blocks x 256 threads; block b -> matrix (b>>12), row (b & 4095)
// ============================================================================
__global__ void __launch_bounds__(256) norm_bf16_kernel(
    const float* __restrict__ emb_i, const float* __restrict__ emb_j) {
    int row = blockIdx.x & (B_ROWS - 1);
    int mat = blockIdx.x >> 12;
    const float4* src = reinterpret_cast<const float4*>(mat ? emb_j : emb_i)
                        + (size_t)row * (D_DIM / 4);
    char* dstBase = reinterpret_cast<char*>(mat ? g_zj : g_zi);
    int t = threadIdx.x;   // handles elements 4t..4t+3 of this row
    float4 v = src[t];
    float ss = v.x * v.x + v.y * v.y + v.z * v.z + v.w * v.w;
#pragma unroll
    for (int o = 16; o > 0; o >>= 1) ss += __shfl_xor_sync(0xFFFFFFFFu, ss, o);
    __shared__ float ws[8];
    if ((t & 31) == 0) ws[t >> 5] = ss;
    __syncthreads();
    float tot = 0.0f;
#pragma unroll
    for (int w = 0; w < 8; w++) tot += ws[w];
    float inv = 1.0f / fmaxf(sqrtf(tot), 1e-12f);

    __nv_bfloat162 lo = __floats2bfloat162_rn(v.x * inv, v.y * inv);
    __nv_bfloat162 hi = __floats2bfloat162_rn(v.z * inv, v.w * inv);
    uint2 pack;
    pack.x = *reinterpret_cast<uint32_t*>(&lo);
    pack.y = *reinterpret_cast<uint32_t*>(&hi);

    int chunk = t >> 4;                               // 64-elem K-chunk index
    uint32_t off = (uint32_t)row * 128u + (uint32_t)(t & 15) * 8u;
    off = SWZ128(off);                                // pre-swizzle in GMEM
    *reinterpret_cast<uint2*>(dstBase + (size_t)chunk * CHUNK_MAT_BYTES + off) = pack;
}

// ============================================================================
// Kernel 2: fused bf16 mma.sync GEMM + softplus + reduce
// grid (32, 16): blockIdx.x = tn (TN=128), blockIdx.y = tm (TM=256)
// 512 threads = 16 warps (8 in M x 2 in N), warp tile 32x64.
// 3-stage cp.async pipeline (commit/wait groups — base sm_80 path).
// ============================================================================
__device__ __forceinline__ void issue_chunk(uint32_t dA, uint32_t dB,
                                            const char* srcA, const char* srcB,
                                            int tid) {
    // A tile 32768B = 2048 x 16B slices -> 4 per thread
#pragma unroll
    for (int i = 0; i < 4; i++) {
        uint32_t idx = (uint32_t)tid + 512u * i;
        cp_async16(dA + idx * 16u, srcA + (size_t)idx * 16u);
    }
    // B tile 16384B = 1024 x 16B slices -> 2 per thread
#pragma unroll
    for (int i = 0; i < 2; i++) {
        uint32_t idx = (uint32_t)tid + 512u * i;
        cp_async16(dB + idx * 16u, srcB + (size_t)idx * 16u);
    }
    CP_COMMIT();
}

__global__ void __launch_bounds__(512, 1) gemm_loss_kernel() {
    extern __shared__ __align__(1024) char smem[];
    uint32_t sb = smem_to_u32(smem);
    int tid = threadIdx.x;
    int wid = tid >> 5, lane = tid & 31;
    int wm = wid >> 1, wn = wid & 1;        // 8 x 2 warp grid
    int tn = blockIdx.x, tm = blockIdx.y;

    uint32_t stA[NSTAGE], stB[NSTAGE];
#pragma unroll
    for (int s = 0; s < NSTAGE; s++) {
        stA[s] = sb + 1024 + s * STAGE_BYTES;
        stB[s] = stA[s] + A_TILE_BYTES;
    }

    const char* gA = reinterpret_cast<const char*>(g_zj) + (size_t)tm * TM * 128;
    const char* gB = reinterpret_cast<const char*>(g_zi) + (size_t)tn * TN * 128;

    // Prologue: chunks 0,1,2 into stages 0,1,2
#pragma unroll
    for (int c = 0; c < NSTAGE; c++)
        issue_chunk(stA[c], stB[c], gA + (size_t)c * CHUNK_MAT_BYTES,
                    gB + (size_t)c * CHUNK_MAT_BYTES, tid);

    // Unswizzled ldmatrix byte offsets (swizzle applied per access so the
    // +kk*32 column advance happens BEFORE the XOR — no carry corruption).
    uint32_t aRow[2];
    {
        int r = lane & 15, hb = (lane >> 4) * 16;
#pragma unroll
        for (int i = 0; i < 2; i++)
            aRow[i] = (uint32_t)(wm * 32 + i * 16 + r) * 128u + hb;
    }
    uint32_t bRow[4];
    {
        int rn = (lane & 7) + ((lane >> 4) << 3);
        int bb = ((lane >> 3) & 1) * 16;
#pragma unroll
        for (int j2 = 0; j2 < 4; j2++)
            bRow[j2] = (uint32_t)(wn * 64 + j2 * 16 + rn) * 128u + bb;
    }

    float acc[64];
#pragma unroll
    for (int i = 0; i < 64; i++) acc[i] = 0.0f;

    int s = 0;
    for (int c = 0; c < NCHUNK; c++) {
        CP_WAIT(NSTAGE - 1);   // oldest pending group (chunk c) complete
        __syncthreads();       // tile fully resident across all threads
        uint32_t baseA = stA[s], baseB = stB[s];
#pragma unroll
        for (int kk = 0; kk < 4; kk++) {
            uint32_t af[2][4], bf[4][4];
            ldsm_x4(af[0], baseA + SWZ128(aRow[0] + kk * 32u));
            ldsm_x4(af[1], baseA + SWZ128(aRow[1] + kk * 32u));
#pragma unroll
            for (int j2 = 0; j2 < 4; j2++)
                ldsm_x4(bf[j2], baseB + SWZ128(bRow[j2] + kk * 32u));
#pragma unroll
            for (int i = 0; i < 2; i++)
#pragma unroll
                for (int j = 0; j < 8; j++)
                    mma16816(&acc[(i * 8 + j) * 4], af[i], &bf[j >> 1][(j & 1) * 2]);
        }
        __syncthreads();       // all warps done reading stage s
        if (c + NSTAGE < NCHUNK)
            issue_chunk(stA[s], stB[s],
                        gA + (size_t)(c + NSTAGE) * CHUNK_MAT_BYTES,
                        gB + (size_t)(c + NSTAGE) * CHUNK_MAT_BYTES, tid);
        s = (s == NSTAGE - 1) ? 0 : s + 1;
    }

    // ---- fused epilogue: softplus + diagonal split, all in registers ----
    int g = lane >> 2, tig = lane & 3;
    int rowBase = tm * TM + wm * 32;
    int colBase = tn * TN + wn * 64;
    float negs = 0.0f, poss = 0.0f;
#pragma unroll
    for (int i = 0; i < 2; i++) {
#pragma unroll
        for (int j = 0; j < 8; j++) {
            const float* d = &acc[(i * 8 + j) * 4];
#pragma unroll
            for (int r = 0; r < 4; r++) {
                int row = rowBase + i * 16 + g + (r >> 1) * 8;
                int col = colBase + j * 8 + tig * 2 + (r & 1);
                float v = d[r];
                if (row == col) poss += __logf(1.0f + __expf(TEMP - v));
                else            negs += __logf(1.0f + __expf(v - TEMP));
            }
        }
    }
#pragma unroll
    for (int o = 16; o > 0; o >>= 1) {
        negs += __shfl_xor_sync(0xFFFFFFFFu, negs, o);
        poss += __shfl_xor_sync(0xFFFFFFFFu, poss, o);
    }
    float* red = reinterpret_cast<float*>(smem + 32);
    if (lane == 0) { red[wid] = negs; red[16 + wid] = poss; }
    __syncthreads();
    if (tid == 0) {
        float n = 0.0f, p = 0.0f;
#pragma unroll
        for (int w = 0; w < 16; w++) { n += red[w]; p += red[16 + w]; }
        int cta = tm * 32 + tn;
        g_partials[cta * 2]     = n;
        g_partials[cta * 2 + 1] = p;
    }
}

// ============================================================================
// Kernel 3: deterministic final reduction of 512 CTA partials -> scalar loss
// ============================================================================
__global__ void __launch_bounds__(512) finalize_kernel(float* __restrict__ out) {
    __shared__ double s[512];
    int t = threadIdx.x;
    double n = (double)g_partials[t * 2];
    double p = (double)g_partials[t * 2 + 1];
    s[t] = n;
    __syncthreads();
    for (int o = 256; o > 0; o >>= 1) {
        if (t < o) s[t] += s[t + o];
        __syncthreads();
    }
    double ntot = s[0];
    __syncthreads();
    s[t] = p;
    __syncthreads();
    for (int o = 256; o > 0; o >>= 1) {
        if (t < o) s[t] += s[t + o];
        __syncthreads();
    }
    double ptot = s[0];
    if (t == 0) {
        const double Bd = (double)B_ROWS;
        double loss = 0.5 * (ptot / Bd) + 0.5 * (ntot / (Bd * (Bd - 1.0)));
        out[0] = (float)loss;
    }
}

// ============================================================================
// Launcher
// ============================================================================
extern "C" void kernel_launch(void* const* d_in, const int* in_sizes, int n_in,
                              void* d_out, int out_size) {
    (void)in_sizes; (void)n_in; (void)out_size;
    const float* emb_i = (const float*)d_in[0];
    const float* emb_j = (const float*)d_in[1];
    float* out = (float*)d_out;

    cudaFuncSetAttribute(gemm_loss_kernel,
                         cudaFuncAttributeMaxDynamicSharedMemorySize, SMEM_TOTAL);

    norm_bf16_kernel<<<2 * B_ROWS, 256>>>(emb_i, emb_j);
    dim3 grid(B_ROWS / TN, B_ROWS / TM);   // (32, 16)
    gemm_loss_kernel<<<grid, 512, SMEM_TOTAL>>>();
    finalize_kernel<<<1, 512>>>(out);
}

// round 10
// speedup vs baseline: 1.0147x; 1.0147x over previous
#include <cuda_runtime.h>
#include <cuda_bf16.h>
#include <cstdint>

// ============================================================================
// Problem constants
// ============================================================================
#define B_ROWS 4096
#define D_DIM  1024
#define TEMP   0.2f

// GEMM tiling: sim[4096,4096] = z_j (M side) @ z_i^T (N side)
#define TM 256
#define TN 128
#define KC 64                            // bf16 per K-chunk = 128 bytes/row
#define NCHUNK (D_DIM / KC)              // 16
#define CHUNK_MAT_BYTES (B_ROWS * 128)   // 524288 bytes per chunk-slab per matrix

#define A_TILE_BYTES (TM * 128)          // 32768
#define B_TILE_BYTES (TN * 128)          // 16384
#define STAGE_BYTES  (A_TILE_BYTES + B_TILE_BYTES)   // 49152
#define NSTAGE 4

// SMEM: [0..1024) control/reduction, then 4 stages of (A tile | B tile)
#define SMEM_TOTAL (1024 + NSTAGE * STAGE_BYTES)     // 197632

#define N_CTAS ((B_ROWS / TM) * (B_ROWS / TN))       // 16 * 32 = 512

// ============================================================================
// Device scratch (static __device__ globals — no allocation allowed)
// Layout: chunk-major, pre-swizzled (SW128): within chunk slab,
//   byte offset = SWZ128(row*128 + kbyte). cp.async copies verbatim and smem
//   lands ldmatrix-ready with zero bank conflicts.
// ============================================================================
__device__ __align__(1024) __nv_bfloat16 g_zj[(size_t)B_ROWS * D_DIM];  // M side (emb_j)
__device__ __align__(1024) __nv_bfloat16 g_zi[(size_t)B_ROWS * D_DIM];  // N side (emb_i)
__device__ float g_partials[2 * N_CTAS];

// ============================================================================
// PTX helpers — base-target only (sm_80-class): cp.async, ldmatrix, mma.sync
// ============================================================================
__device__ __forceinline__ uint32_t smem_to_u32(const void* smem_ptr) {
    uint32_t addr;
    asm("{ .reg .u64 tmp; cvta.to.shared.u64 tmp, %1; cvt.u32.u64 %0, tmp; }"
        : "=r"(addr) : "l"(smem_ptr));
    return addr;
}

#define SWZ128(o) ((o) ^ (((o) >> 3) & 0x70))

__device__ __forceinline__ void cp_async16(uint32_t dst, const void* src) {
    asm volatile("cp.async.cg.shared.global [%0], [%1], 16;"
        :: "r"(dst), "l"(src) : "memory");
}
#define CP_COMMIT() asm volatile("cp.async.commit_group;" ::: "memory")
#define CP_WAIT(n)  asm volatile("cp.async.wait_group %0;" :: "n"(n) : "memory")

__device__ __forceinline__ void ldsm_x4(uint32_t* r, uint32_t addr) {
    asm volatile("ldmatrix.sync.aligned.m8n8.x4.shared.b16 {%0,%1,%2,%3}, [%4];"
        : "=r"(r[0]), "=r"(r[1]), "=r"(r[2]), "=r"(r[3]) : "r"(addr));
}

__device__ __forceinline__ void mma16816(float* d, const uint32_t* a, const uint32_t* b) {
    asm volatile(
        "mma.sync.aligned.m16n8k16.row.col.f32.bf16.bf16.f32 "
        "{%0,%1,%2,%3}, {%4,%5,%6,%7}, {%8,%9}, {%0,%1,%2,%3};"
        : "+f"(d[0]), "+f"(d[1]), "+f"(d[2]), "+f"(d[3])
        : "r"(a[0]), "r"(a[1]), "r"(a[2]), "r"(a[3]), "r"(b[0]), "r"(b[1]));
}

// ============================================================================
// Kernel 1: row L2-normalize fp32 -> bf16 scratch (chunk-major, pre-swizzled)
// 4096 blocks x 256 threads; block b -> matrix (b>>11), rows 2*(b&2047)+{0,1}
// Each 128-thread half handles one row: 8 elements (2 float4) per thread,
// one uint4 (8 bf16) swizzled store per thread.
// ============================================================================
__global__ void __launch_bounds__(256) norm_bf16_kernel(
    const float* __restrict__ emb_i, const float* __restrict__ emb_j) {
    int t = threadIdx.x;
    int half = t >> 7;                       // row within block
    int q = t & 127;                         // element-octet index within row
    int mat = blockIdx.x >> 11;
    int row = ((blockIdx.x & 2047) << 1) + half;

    const float4* src = reinterpret_cast<const float4*>(mat ? emb_j : emb_i)
                        + (size_t)row * (D_DIM / 4);
    char* dstBase = reinterpret_cast<char*>(mat ? g_zj : g_zi);

    float4 v0 = src[2 * q];
    float4 v1 = src[2 * q + 1];
    float ss = v0.x * v0.x + v0.y * v0.y + v0.z * v0.z + v0.w * v0.w
             + v1.x * v1.x + v1.y * v1.y + v1.z * v1.z + v1.w * v1.w;
#pragma unroll
    for (int o = 16; o > 0; o >>= 1) ss += __shfl_xor_sync(0xFFFFFFFFu, ss, o);
    __shared__ float ws[8];
    if ((t & 31) == 0) ws[t >> 5] = ss;
    __syncthreads();
    float tot = ws[half * 4] + ws[half * 4 + 1] + ws[half * 4 + 2] + ws[half * 4 + 3];
    float inv = 1.0f / fmaxf(sqrtf(tot), 1e-12f);

    __nv_bfloat162 p0 = __floats2bfloat162_rn(v0.x * inv, v0.y * inv);
    __nv_bfloat162 p1 = __floats2bfloat162_rn(v0.z * inv, v0.w * inv);
    __nv_bfloat162 p2 = __floats2bfloat162_rn(v1.x * inv, v1.y * inv);
    __nv_bfloat162 p3 = __floats2bfloat162_rn(v1.z * inv, v1.w * inv);
    uint4 pack;
    pack.x = *reinterpret_cast<uint32_t*>(&p0);
    pack.y = *reinterpret_cast<uint32_t*>(&p1);
    pack.z = *reinterpret_cast<uint32_t*>(&p2);
    pack.w = *reinterpret_cast<uint32_t*>(&p3);

    int chunk = q >> 3;                                  // 64-elem K-chunk
    uint32_t off = (uint32_t)row * 128u + (uint32_t)(q & 7) * 16u;
    off = SWZ128(off);                                   // pre-swizzle in GMEM
    *reinterpret_cast<uint4*>(dstBase + (size_t)chunk * CHUNK_MAT_BYTES + off) = pack;
}

// ============================================================================
// Kernel 2: fused bf16 mma.sync GEMM + softplus + reduce
// grid (32, 16): blockIdx.x = tn (TN=128), blockIdx.y = tm (TM=256)
// 512 threads = 16 warps (8 in M x 2 in N), warp tile 32x64.
// 4-stage cp.async pipeline, ONE __syncthreads per chunk:
//   wait(chunk c) -> sync -> issue chunk c+3 (stage just freed) -> compute c
// commit_group runs EVERY iteration (empty in the tail) so wait_group counts
// stay exact through the last chunks.
// ============================================================================
__device__ __forceinline__ void issue_loads(uint32_t dA, uint32_t dB,
                                            const char* srcA, const char* srcB,
                                            int tid) {
    // A tile 32768B = 2048 x 16B slices -> 4 per thread
#pragma unroll
    for (int i = 0; i < 4; i++) {
        uint32_t idx = (uint32_t)tid + 512u * i;
        cp_async16(dA + idx * 16u, srcA + (size_t)idx * 16u);
    }
    // B tile 16384B = 1024 x 16B slices -> 2 per thread
#pragma unroll
    for (int i = 0; i < 2; i++) {
        uint32_t idx = (uint32_t)tid + 512u * i;
        cp_async16(dB + idx * 16u, srcB + (size_t)idx * 16u);
    }
}

__global__ void __launch_bounds__(512, 1) gemm_loss_kernel() {
    extern __shared__ __align__(1024) char smem[];
    uint32_t sb = smem_to_u32(smem);
    int tid = threadIdx.x;
    int wid = tid >> 5, lane = tid & 31;
    int wm = wid >> 1, wn = wid & 1;        // 8 x 2 warp grid
    int tn = blockIdx.x, tm = blockIdx.y;

    uint32_t stA[NSTAGE], stB[NSTAGE];
#pragma unroll
    for (int s = 0; s < NSTAGE; s++) {
        stA[s] = sb + 1024 + s * STAGE_BYTES;
        stB[s] = stA[s] + A_TILE_BYTES;
    }

    const char* gA = reinterpret_cast<const char*>(g_zj) + (size_t)tm * TM * 128;
    const char* gB = reinterpret_cast<const char*>(g_zi) + (size_t)tn * TN * 128;

    // Prologue: chunks 0..NSTAGE-2 into stages 0..NSTAGE-2 (one group each)
#pragma unroll
    for (int c = 0; c < NSTAGE - 1; c++) {
        issue_loads(stA[c], stB[c], gA + (size_t)c * CHUNK_MAT_BYTES,
                    gB + (size_t)c * CHUNK_MAT_BYTES, tid);
        CP_COMMIT();
    }

    // Unswizzled ldmatrix byte offsets (swizzle applied per access so the
    // +kk*32 column advance happens BEFORE the XOR — no carry corruption).
    uint32_t aRow[2];
    {
        int r = lane & 15, hb = (lane >> 4) * 16;
#pragma unroll
        for (int i = 0; i < 2; i++)
            aRow[i] = (uint32_t)(wm * 32 + i * 16 + r) * 128u + hb;
    }
    uint32_t bRow[4];
    {
        int rn = (lane & 7) + ((lane >> 4) << 3);
        int bb = ((lane >> 3) & 1) * 16;
#pragma unroll
        for (int j2 = 0; j2 < 4; j2++)
            bRow[j2] = (uint32_t)(wn * 64 + j2 * 16 + rn) * 128u + bb;
    }

    float acc[64];
#pragma unroll
    for (int i = 0; i < 64; i++) acc[i] = 0.0f;

    for (int c = 0; c < NCHUNK; c++) {
        CP_WAIT(NSTAGE - 2);   // chunk c's group retired (groups are exact)
        __syncthreads();       // chunk c visible to all; stage (c-1)%4 free

        int cn = c + NSTAGE - 1;
        if (cn < NCHUNK)
            issue_loads(stA[cn & (NSTAGE - 1)], stB[cn & (NSTAGE - 1)],
                        gA + (size_t)cn * CHUNK_MAT_BYTES,
                        gB + (size_t)cn * CHUNK_MAT_BYTES, tid);
        CP_COMMIT();           // unconditional: tail groups may be empty

        uint32_t baseA = stA[c & (NSTAGE - 1)], baseB = stB[c & (NSTAGE - 1)];
#pragma unroll
        for (int kk = 0; kk < 4; kk++) {
            uint32_t af[2][4], bf[4][4];
            ldsm_x4(af[0], baseA + SWZ128(aRow[0] + kk * 32u));
            ldsm_x4(af[1], baseA + SWZ128(aRow[1] + kk * 32u));
#pragma unroll
            for (int j2 = 0; j2 < 4; j2++)
                ldsm_x4(bf[j2], baseB + SWZ128(bRow[j2] + kk * 32u));
#pragma unroll
            for (int i = 0; i < 2; i++)
#pragma unroll
                for (int j = 0; j < 8; j++)
                    mma16816(&acc[(i * 8 + j) * 4], af[i], &bf[j >> 1][(j & 1) * 2]);
        }
    }

    // ---- fused epilogue: softplus + diagonal split, all in registers ----
    int g = lane >> 2, tig = lane & 3;
    int rowBase = tm * TM + wm * 32;
    int colBase = tn * TN + wn * 64;
    float negs = 0.0f, poss = 0.0f;
#pragma unroll
    for (int i = 0; i < 2; i++) {
#pragma unroll
        for (int j = 0; j < 8; j++) {
            const float* d = &acc[(i * 8 + j) * 4];
#pragma unroll
            for (int r = 0; r < 4; r++) {
                int row = rowBase + i * 16 + g + (r >> 1) * 8;
                int col = colBase + j * 8 + tig * 2 + (r & 1);
                float v = d[r];
                if (row == col) poss += __logf(1.0f + __expf(TEMP - v));
                else            negs += __logf(1.0f + __expf(v - TEMP));
            }
        }
    }
#pragma unroll
    for (int o = 16; o > 0; o >>= 1) {
        negs += __shfl_xor_sync(0xFFFFFFFFu, negs, o);
        poss += __shfl_xor_sync(0xFFFFFFFFu, poss, o);
    }
    float* red = reinterpret_cast<float*>(smem + 32);
    if (lane == 0) { red[wid] = negs; red[16 + wid] = poss; }
    __syncthreads();
    if (tid == 0) {
        float n = 0.0f, p = 0.0f;
#pragma unroll
        for (int w = 0; w < 16; w++) { n += red[w]; p += red[16 + w]; }
        int cta = tm * 32 + tn;
        g_partials[cta * 2]     = n;
        g_partials[cta * 2 + 1] = p;
    }
}

// ============================================================================
// Kernel 3: deterministic final reduction of 512 CTA partials -> scalar loss
// ============================================================================
__global__ void __launch_bounds__(512) finalize_kernel(float* __restrict__ out) {
    __shared__ double s[512];
    int t = threadIdx.x;
    double n = (double)g_partials[t * 2];
    double p = (double)g_partials[t * 2 + 1];
    s[t] = n;
    __syncthreads();
    for (int o = 256; o > 0; o >>= 1) {
        if (t < o) s[t] += s[t + o];
        __syncthreads();
    }
    double ntot = s[0];
    __syncthreads();
    s[t] = p;
    __syncthreads();
    for (int o = 256; o > 0; o >>= 1) {
        if (t < o) s[t] += s[t + o];
        __syncthreads();
    }
    double ptot = s[0];
    if (t == 0) {
        const double Bd = (double)B_ROWS;
        double loss = 0.5 * (ptot / Bd) + 0.5 * (ntot / (Bd * (Bd - 1.0)));
        out[0] = (float)loss;
    }
}

// ============================================================================
// Launcher
// ============================================================================
extern "C" void kernel_launch(void* const* d_in, const int* in_sizes, int n_in,
                              void* d_out, int out_size) {
    (void)in_sizes; (void)n_in; (void)out_size;
    const float* emb_i = (const float*)d_in[0];
    const float* emb_j = (const float*)d_in[1];
    float* out = (float*)d_out;

    cudaFuncSetAttribute(gemm_loss_kernel,
                         cudaFuncAttributeMaxDynamicSharedMemorySize, SMEM_TOTAL);

    norm_bf16_kernel<<<4096, 256>>>(emb_i, emb_j);
    dim3 grid(B_ROWS / TN, B_ROWS / TM);   // (32, 16)
    gemm_loss_kernel<<<grid, 512, SMEM_TOTAL>>>();
    finalize_kernel<<<1, 512>>>(out);
}